// round 16
// baseline (speedup 1.0000x reference)
#include <cuda_runtime.h>
#include <cstdint>
#include <math.h>

#define BATCH 2048
#define LEN   4096
#define NT    224              // one row per 224-thread CTA, 7 warps
#define W     20
#define NBLK  207              // 207*20 = 4140 >= 20+4096+19
#define PRE   32               // front guard (-inf); left halo of block 0 -> idx 12
#define ASZ   4224             // PRE + 4180 rounded to 16B multiple
#define DIDX  52               // smem index of signal element i=0 (p=20+i, +PRE)

__device__ float4   g_rowbuf[BATCH];
__device__ unsigned g_count;

// ---------------- warp reductions ----------------
__device__ __forceinline__ double wredD(double v) {
    #pragma unroll
    for (int o = 16; o; o >>= 1) v += __shfl_down_sync(0xffffffffu, v, o);
    return v;
}
__device__ __forceinline__ int wredI(int v) {
    #pragma unroll
    for (int o = 16; o; o >>= 1) v += __shfl_down_sync(0xffffffffu, v, o);
    return v;
}

// vectorized 20-float load (5x LDS.128; base must be 16B-aligned)
__device__ __forceinline__ void ld20(const float* p, float* d) {
    const float4* p4 = (const float4*)p;
    #pragma unroll
    for (int q = 0; q < 5; ++q) {
        float4 t = p4[q];
        d[4*q+0] = t.x; d[4*q+1] = t.y; d[4*q+2] = t.z; d[4*q+3] = t.w;
    }
}

// ---------------- register-resident van Herk block, W=20 vectorized ---------
// Thread owns padded block [s, s+20), s = 20t (16B-aligned stride).
// SL[k] = max(B[k-20 .. -1]) (left-halo suffix), PR[k] = max(B[20 .. 20+k]).
// pooled19 (d10): j<=8 -> max(SL[j+11], c[0..j+9]); j=9/10 fully in-block;
//                 j>=11 -> max(c[j-9..19], PR[j-11]).
// d20 = peak10 && v>=Mfull && v>=SL[j+1] (j<19) && v>=PR[j-1] (j>0).
template<bool P2P>
__device__ __forceinline__ void processBlock(const float* __restrict__ A, int s,
                                             unsigned& mask, int& cnt20,
                                             const float* __restrict__ X,
                                             unsigned maskx, float& pp) {
    const float* B = A + PRE + s;

    float SL[20];                 // SL[1..19] used; SL[19] = B[-1]
    {
        float L[20];
        ld20(B - 20, L);
        SL[19] = L[19];
        #pragma unroll
        for (int k = 18; k >= 1; --k) SL[k] = fmaxf(L[k], SL[k + 1]);
    }
    float c[20];
    ld20(B, c);
    float PR[19];                 // PR[0..18]
    {
        float R[20];
        ld20(B + 20, R);
        PR[0] = R[0];
        #pragma unroll
        for (int k = 1; k <= 18; ++k) PR[k] = fmaxf(PR[k - 1], R[k]);
    }

    float mA = c[0];
    #pragma unroll
    for (int k = 1; k <= 8; ++k) mA = fmaxf(mA, c[k]);      // max(c[0..8])
    float Mf = mA;
    #pragma unroll
    for (int k = 9; k <= 19; ++k) Mf = fmaxf(Mf, c[k]);     // block max

    unsigned m10 = 0u, m20 = 0u;

    // ---- left: j = 0..8, then j = 9
    {
        float m = mA;
        #pragma unroll
        for (int j = 0; j <= 8; ++j) {
            m = fmaxf(m, c[j + 9]);                         // max(c[0..j+9])
            const float v = c[j];
            const float left = (j == 0) ? SL[19] : c[j - 1];
            const float nb = fmaxf(left, c[j + 1]);
            if (v > nb && v >= fmaxf(m, SL[j + 11])) {
                m10 |= (1u << j);
                float dm = fmaxf(Mf, SL[j + 1]);
                if (j > 0) dm = fmaxf(dm, PR[j - 1]);
                if (v >= dm) m20 |= (1u << j);
            }
        }
        m = fmaxf(m, c[18]);                                // max(c[0..18])
        const float v = c[9];
        const float nb = fmaxf(c[8], c[10]);
        if (v > nb && v >= m) {
            m10 |= (1u << 9);
            if (v >= fmaxf(fmaxf(Mf, SL[10]), PR[8])) m20 |= (1u << 9);
        }
    }
    // ---- right: j = 19..11, then j = 10
    {
        float m = c[19];
        #pragma unroll
        for (int k = 18; k >= 10; --k) m = fmaxf(m, c[k]);  // max(c[10..19])
        #pragma unroll
        for (int j = 19; j >= 11; --j) {
            const float v = c[j];
            const float right = (j == 19) ? PR[0] : c[j + 1];
            const float nb = fmaxf(c[j - 1], right);
            if (v > nb && v >= fmaxf(m, PR[j - 11])) {
                m10 |= (1u << j);
                float dm = fmaxf(Mf, PR[j - 1]);
                if (j < 19) dm = fmaxf(dm, SL[j + 1]);
                if (v >= dm) m20 |= (1u << j);
            }
            m = fmaxf(m, c[j - 10]);                        // extend window
        }
        const float v = c[10];                              // window [1,19]
        const float nb = fmaxf(c[9], c[11]);
        if (v > nb && v >= m) {
            m10 |= (1u << 10);
            if (v >= fmaxf(fmaxf(Mf, SL[11]), PR[9])) m20 |= (1u << 10);
        }
    }

    // edge corrections: i=0 at (s=20, j=0); i=LEN-1 at (s=4100, j=15)
    if (s == 20)   { m10 &= ~1u;         m20 &= ~1u;         }
    if (s == 4100) { m10 &= ~(1u << 15); m20 &= ~(1u << 15); }

    mask = m10;
    cnt20 = __popc(m20);

    if (P2P) {  // sparse: nonzero terms only where either signal has a peak
        unsigned un = maskx | mask;
        while (un) {
            const int j = __ffs(un) - 1;
            un &= un - 1;
            const float pkx = ((maskx >> j) & 1u) ? X[PRE + s + j] : 0.f;
            const float pky = ((mask  >> j) & 1u) ? B[j] : 0.f;
            const float d = pkx - pky;
            pp += d * d;
        }
    }
}

// ---------------- main kernel: 1 row per 224-thread CTA ----------------
__global__ void __launch_bounds__(NT, 4)
loss_kernel(const float* __restrict__ xg, const float* __restrict__ yg,
            float* __restrict__ out) {
    __shared__ __align__(16) float xs[ASZ];
    __shared__ __align__(16) float ys[ASZ];
    __shared__ double redd[7 * 4];
    __shared__ int    redi[7 * 2];
    __shared__ int    s_isLast;

    const int tid  = threadIdx.x;
    const int lane = tid & 31;
    const int wid  = tid >> 5;
    const int row  = blockIdx.x;

    // -inf guards: idx [0,52) and [4148, 4212)  (116 slots, one shot)
    if (tid < 116) {
        const int idx = (tid < 52) ? tid : 4148 + (tid - 52);
        xs[idx] = -INFINITY;
        ys[idx] = -INFINITY;
    }

    // Phase 1: coalesced load + fp32 elementwise partials (dot + norms only;
    // sum of squared diffs recovered as nx - 2*dt + ny in fp64 at combine).
    const float4* x4 = (const float4*)(xg + (size_t)row * LEN);
    const float4* y4 = (const float4*)(yg + (size_t)row * LEN);
    float4* xs4 = (float4*)(xs + DIDX);
    float4* ys4 = (float4*)(ys + DIDX);
    float fdt = 0.f, fnx = 0.f, fny = 0.f;
    #pragma unroll
    for (int k = 0; k < 5; ++k) {
        const int j = tid + k * NT;
        if (k < 4 || j < LEN / 4) {
            float4 a = x4[j], b = y4[j];
            xs4[j] = a; ys4[j] = b;
            fdt += a.x*b.x + a.y*b.y + a.z*b.z + a.w*b.w;
            fnx += a.x*a.x + a.y*a.y + a.z*a.z + a.w*a.w;
            fny += b.x*b.x + b.y*b.y + b.z*b.z + b.w*b.w;
        }
    }
    __syncthreads();                                   // B1: row resident

    // Phase 2: per-thread block processing, x then y (registers only)
    int cx = 0, cy = 0;
    float fpp = 0.f;
    if (tid < NBLK) {
        const int s = tid * W;
        unsigned mx, my;
        int c20;
        processBlock<false>(xs, s, mx, c20, ys, 0u, fpp);
        cx = c20;
        processBlock<true>(ys, s, my, c20, xs, mx, fpp);
        cy = c20;
    }

    // Phase 3: combined block reduction (4 doubles + 2 ints, 7 warps)
    double vals[4] = {(double)fdt, (double)fnx, (double)fny, (double)fpp};
    #pragma unroll
    for (int k = 0; k < 4; ++k) vals[k] = wredD(vals[k]);
    cx = wredI(cx);
    cy = wredI(cy);
    if (lane == 0) {
        #pragma unroll
        for (int k = 0; k < 4; ++k) redd[wid * 4 + k] = vals[k];
        redi[wid * 2 + 0] = cx;
        redi[wid * 2 + 1] = cy;
    }
    __syncthreads();                                   // B2

    if (tid == 0) {
        double dt = 0, nx = 0, ny = 0, pp = 0;
        int tcx = 0, tcy = 0;
        #pragma unroll
        for (int w = 0; w < NT / 32; ++w) {
            dt += redd[w * 4 + 0]; nx += redd[w * 4 + 1];
            ny += redd[w * 4 + 2]; pp += redd[w * 4 + 3];
            tcx += redi[w * 2 + 0]; tcy += redi[w * 2 + 1];
        }
        const double sd = nx - 2.0 * dt + ny;          // sum (a-b)^2
        const double mse_i = sd / (double)LEN;
        const double p2p_i = pp / (double)LEN;
        const double cosv  = dt / (sqrt(nx) * sqrt(ny));
        const double custom = (tcx != tcy) ? mse_i : 0.5 * p2p_i;  // ALPHA=1, BETA=0.5
        float4 r;
        r.x = (float)sd; r.y = (float)cosv; r.z = (float)pp; r.w = (float)custom;
        g_rowbuf[row] = r;
        __threadfence();
        s_isLast = (atomicAdd(&g_count, 1u) == BATCH - 1);
    }
    __syncthreads();                                   // B3

    // Phase 4: last CTA performs the deterministic final reduction
    if (s_isLast) {
        double s0 = 0, s1 = 0, s2 = 0, s3 = 0;
        for (int r = tid; r < BATCH; r += NT) {
            float4 p = g_rowbuf[r];
            s0 += (double)p.x; s1 += (double)p.y;
            s2 += (double)p.z; s3 += (double)p.w;
        }
        s0 = wredD(s0); s1 = wredD(s1); s2 = wredD(s2); s3 = wredD(s3);
        if (lane == 0) {
            redd[wid * 4 + 0] = s0; redd[wid * 4 + 1] = s1;
            redd[wid * 4 + 2] = s2; redd[wid * 4 + 3] = s3;
        }
        __syncthreads();
        if (tid == 0) {
            double t0 = 0, t1 = 0, t2s = 0, t3 = 0;
            #pragma unroll
            for (int w = 0; w < NT / 32; ++w) {
                t0 += redd[w * 4 + 0]; t1 += redd[w * 4 + 1];
                t2s += redd[w * 4 + 2]; t3 += redd[w * 4 + 3];
            }
            const double mse = t0 / ((double)BATCH * (double)LEN);
            out[0] = (float)(mse + t3);               // total_loss
            out[1] = (float)(t1 / (double)BATCH);     // cosine_similarity
            out[2] = (float)(t2s / (double)LEN);      // p2p_loss
            out[3] = (float)mse;                      // mse_loss
            g_count = 0;                              // reset for next replay
        }
    }
}

extern "C" void kernel_launch(void* const* d_in, const int* in_sizes, int n_in,
                              void* d_out, int out_size) {
    const float* x = (const float*)d_in[0];   // in_signal  [2048, 4096] f32
    const float* y = (const float*)d_in[1];   // ref_signal [2048, 4096] f32
    float* out = (float*)d_out;
    loss_kernel<<<BATCH, NT>>>(x, y, out);
}